// round 6
// baseline (speedup 1.0000x reference)
#include <cuda_runtime.h>

#define NN   50000
#define EE   800000
#define FIN  128
#define FHID 256
#define FOUT 128
#define ETOT (EE + NN)

typedef unsigned long long ull;

// ---------------- device scratch (no allocations allowed) ----------------
__device__ int   g_is64;
__device__ int   g_ei[2 * EE];               // decoded edge_index (int32)
__device__ int   g_deg[NN];
__device__ int   g_rowptr[NN + 1];
__device__ int   g_cursor[NN];
__device__ int   g_col[ETOT];
__device__ float g_w[ETOT];
__device__ float g_dis[NN];
__device__ float g_agg1[(size_t)NN * FIN];   // 25.6 MB
__device__ float g_h1[(size_t)NN * FHID];    // 51.2 MB
__device__ float g_g2[(size_t)NN * FOUT];    // 25.6 MB

// ---------------- packed f32x2 helpers (FFMA2: PTX-only on sm_103a) ----------------
__device__ __forceinline__ ull ffma2(ull a, ull b, ull c) {
    ull d;
    asm("fma.rn.f32x2 %0, %1, %2, %3;" : "=l"(d) : "l"(a), "l"(b), "l"(c));
    return d;
}
__device__ __forceinline__ ull dup2(float a) {
    ull d; unsigned r = __float_as_uint(a);
    asm("mov.b64 %0, {%1, %1};" : "=l"(d) : "r"(r));
    return d;
}
__device__ __forceinline__ float2 unpack2(ull v) {
    unsigned lo, hi;
    asm("mov.b64 {%0, %1}, %2;" : "=r"(lo), "=r"(hi) : "l"(v));
    return make_float2(__uint_as_float(lo), __uint_as_float(hi));
}

// ---------------- edge_index dtype detection + decode (+degree count) --------------
__global__ void k_detect(const int* __restrict__ ei_raw) {
    if (threadIdx.x == 0) {
        int is64 = 1;
        for (int i = 1; i < 64; i += 2)
            if (ei_raw[i] != 0) { is64 = 0; break; }
        g_is64 = is64;
    }
}

__global__ void k_deg_init() {
    int i = blockIdx.x * blockDim.x + threadIdx.x;
    if (i < NN) g_deg[i] = 1;  // self-loop
}

// decode + fused dst-degree counting (saves a full pass over g_ei)
__global__ void k_decode(const int* __restrict__ ei_raw) {
    int e = blockIdx.x * blockDim.x + threadIdx.x;
    if (e >= 2 * EE) return;
    int v = g_is64 ? ei_raw[2 * e] : ei_raw[e];
    v = min(max(v, 0), NN - 1);   // defensive clamp
    g_ei[e] = v;
    if (e >= EE) atomicAdd(&g_deg[v], 1);   // dst half
}

// single-block exclusive scan of g_deg -> g_rowptr ; also emits g_dis
__global__ void k_scan() {
    __shared__ int sh[1024];
    int t = threadIdx.x;
    const int CH = (NN + 1023) / 1024;  // 49
    int s = t * CH;
    int e = min(s + CH, NN);
    int sum = 0;
    for (int i = s; i < e; i++) sum += g_deg[i];
    sh[t] = sum;
    __syncthreads();
    for (int off = 1; off < 1024; off <<= 1) {
        int v = (t >= off) ? sh[t - off] : 0;
        __syncthreads();
        sh[t] += v;
        __syncthreads();
    }
    int prefix = (t > 0) ? sh[t - 1] : 0;
    for (int i = s; i < e; i++) {
        int d = g_deg[i];
        g_rowptr[i] = prefix;
        g_cursor[i] = prefix;
        g_dis[i]    = rsqrtf((float)d);
        prefix += d;
    }
    if (t == 1023) g_rowptr[NN] = sh[1023];
}

__global__ void k_fill() {
    int e = blockIdx.x * blockDim.x + threadIdx.x;
    if (e >= ETOT) return;
    int s, d;
    if (e < EE) { s = g_ei[e]; d = g_ei[EE + e]; }
    else        { s = d = e - EE; }            // self-loop edges
    int pos = atomicAdd(&g_cursor[d], 1);
    g_col[pos] = s;
    g_w[pos]   = g_dis[s] * g_dis[d];
}

// ---------------- SpMM: out[r,:] = sum_e w[e] * in[col[e],:]  (F = 128) -------------
template <int LAYER>
__global__ void k_spmm128(const float* __restrict__ xin, float* __restrict__ xout,
                          const float* __restrict__ bias) {
    const float* in  = (LAYER == 1) ? xin : (const float*)g_g2;
    float*       out = (LAYER == 1) ? (float*)g_agg1 : xout;

    int warp = (blockIdx.x * blockDim.x + threadIdx.x) >> 5;
    int lane = threadIdx.x & 31;
    if (warp >= NN) return;
    int start = g_rowptr[warp];
    int end   = g_rowptr[warp + 1];
    const float4* in4 = (const float4*)in;
    float4 acc = make_float4(0.f, 0.f, 0.f, 0.f);

    for (int e0 = start; e0 < end; e0 += 32) {
        int e = e0 + lane;
        int   c  = 0;
        float wv = 0.f;
        if (e < end) { c = g_col[e]; wv = g_w[e]; }
        int cnt = min(32, end - e0);
        for (int j = 0; j < cnt; j++) {
            int   cj = __shfl_sync(0xffffffffu, c,  j);
            float wj = __shfl_sync(0xffffffffu, wv, j);
            float4 v = __ldg(&in4[(size_t)cj * 32 + lane]);
            acc.x = fmaf(wj, v.x, acc.x);
            acc.y = fmaf(wj, v.y, acc.y);
            acc.z = fmaf(wj, v.z, acc.z);
            acc.w = fmaf(wj, v.w, acc.w);
        }
    }
    if (LAYER == 2) {  // fuse bias + relu
        float4 b = ((const float4*)bias)[lane];
        acc.x = fmaxf(acc.x + b.x, 0.f);
        acc.y = fmaxf(acc.y + b.y, 0.f);
        acc.z = fmaxf(acc.z + b.z, 0.f);
        acc.w = fmaxf(acc.w + b.w, 0.f);
    }
    ((float4*)out)[(size_t)warp * 32 + lane] = acc;
}

// ---------------- GEMM via FFMA2: C[M,NCOL] = A[M,K] @ B[K,NCOL] --------------------
// BM=128, BN=128, BK=16, 256 threads, 8x8 micro-tile, f32x2-packed over N-pairs.
// Double-buffered smem with register prefetch.
template <int LAYER, int K, int NCOL>
__global__ __launch_bounds__(256, 2) void k_gemm2(
    const float* __restrict__ B, const float* __restrict__ bias) {
    const float* A = (LAYER == 1) ? (const float*)g_agg1 : (const float*)g_h1;
    float*       C = (LAYER == 1) ? (float*)g_h1 : (float*)g_g2;
    const int M = NN;
    const int NT = K / 16;   // k-tiles

    __shared__ float As[2][16][132];   // padded: transpose-store conflicts tolerable
    __shared__ float Bs[2][16][128];

    int t  = threadIdx.x;
    int tx = t & 15;   // 16 -> 8 cols each (4 f32x2 pairs)
    int ty = t >> 4;   // 16 -> 8 rows each
    int m0 = blockIdx.y * 128;
    int n0 = blockIdx.x * 128;

    // A loader mapping: row = t>>1 within tile, kseg = (t&1)*8 (8 floats)
    int a_m   = t >> 1;
    int a_k   = (t & 1) * 8;
    int a_row = m0 + a_m;
    // B loader mapping: krow = t>>4, 8 floats at (t&15)*8
    int b_k = t >> 4;
    int b_c = (t & 15) * 8;

    ull acc[8][4];
#pragma unroll
    for (int i = 0; i < 8; i++)
#pragma unroll
        for (int j = 0; j < 4; j++) acc[i][j] = 0ull;

    float4 pa0, pa1, pb0, pb1;

    // ---- load tile 0 ----
    {
        pa0 = make_float4(0.f, 0.f, 0.f, 0.f); pa1 = pa0;
        if (a_row < M) {
            pa0 = *(const float4*)&A[(size_t)a_row * K + a_k];
            pa1 = *(const float4*)&A[(size_t)a_row * K + a_k + 4];
        }
        pb0 = *(const float4*)&B[(size_t)b_k * NCOL + n0 + b_c];
        pb1 = *(const float4*)&B[(size_t)b_k * NCOL + n0 + b_c + 4];
        As[0][a_k + 0][a_m] = pa0.x; As[0][a_k + 1][a_m] = pa0.y;
        As[0][a_k + 2][a_m] = pa0.z; As[0][a_k + 3][a_m] = pa0.w;
        As[0][a_k + 4][a_m] = pa1.x; As[0][a_k + 5][a_m] = pa1.y;
        As[0][a_k + 6][a_m] = pa1.z; As[0][a_k + 7][a_m] = pa1.w;
        *(float4*)&Bs[0][b_k][b_c]     = pb0;
        *(float4*)&Bs[0][b_k][b_c + 4] = pb1;
    }
    __syncthreads();

    for (int tt = 0; tt < NT; tt++) {
        int cur = tt & 1;
        // ---- prefetch next tile into registers ----
        if (tt + 1 < NT) {
            int kk = (tt + 1) * 16;
            pa0 = make_float4(0.f, 0.f, 0.f, 0.f); pa1 = pa0;
            if (a_row < M) {
                pa0 = *(const float4*)&A[(size_t)a_row * K + kk + a_k];
                pa1 = *(const float4*)&A[(size_t)a_row * K + kk + a_k + 4];
            }
            pb0 = *(const float4*)&B[(size_t)(kk + b_k) * NCOL + n0 + b_c];
            pb1 = *(const float4*)&B[(size_t)(kk + b_k) * NCOL + n0 + b_c + 4];
        }
        // ---- compute current tile ----
#pragma unroll
        for (int k = 0; k < 16; k++) {
            float4 aA = *(const float4*)&As[cur][k][ty * 8];
            float4 aB = *(const float4*)&As[cur][k][ty * 8 + 4];
            ulonglong2 bA = *(const ulonglong2*)&Bs[cur][k][tx * 8];
            ulonglong2 bB = *(const ulonglong2*)&Bs[cur][k][tx * 8 + 4];
            ull b0 = bA.x, b1 = bA.y, b2 = bB.x, b3 = bB.y;
            float av[8] = {aA.x, aA.y, aA.z, aA.w, aB.x, aB.y, aB.z, aB.w};
#pragma unroll
            for (int i = 0; i < 8; i++) {
                ull ad = dup2(av[i]);
                acc[i][0] = ffma2(ad, b0, acc[i][0]);
                acc[i][1] = ffma2(ad, b1, acc[i][1]);
                acc[i][2] = ffma2(ad, b2, acc[i][2]);
                acc[i][3] = ffma2(ad, b3, acc[i][3]);
            }
        }
        // ---- store prefetched regs to other buffer ----
        if (tt + 1 < NT) {
            int nxt = cur ^ 1;
            As[nxt][a_k + 0][a_m] = pa0.x; As[nxt][a_k + 1][a_m] = pa0.y;
            As[nxt][a_k + 2][a_m] = pa0.z; As[nxt][a_k + 3][a_m] = pa0.w;
            As[nxt][a_k + 4][a_m] = pa1.x; As[nxt][a_k + 5][a_m] = pa1.y;
            As[nxt][a_k + 6][a_m] = pa1.z; As[nxt][a_k + 7][a_m] = pa1.w;
            *(float4*)&Bs[nxt][b_k][b_c]     = pb0;
            *(float4*)&Bs[nxt][b_k][b_c + 4] = pb1;
        }
        __syncthreads();
    }

    // ---- epilogue: unpack, bias+relu (layer 1), store 2x float4 per row ----
    int colb = n0 + tx * 8;
    float4 bv0 = make_float4(0.f, 0.f, 0.f, 0.f), bv1 = bv0;
    if (LAYER == 1) {
        bv0 = *(const float4*)&bias[colb];
        bv1 = *(const float4*)&bias[colb + 4];
    }
#pragma unroll
    for (int i = 0; i < 8; i++) {
        int row = m0 + ty * 8 + i;
        if (row >= M) continue;
        float2 c01 = unpack2(acc[i][0]);
        float2 c23 = unpack2(acc[i][1]);
        float2 c45 = unpack2(acc[i][2]);
        float2 c67 = unpack2(acc[i][3]);
        float4 o0 = make_float4(c01.x, c01.y, c23.x, c23.y);
        float4 o1 = make_float4(c45.x, c45.y, c67.x, c67.y);
        if (LAYER == 1) {
            o0.x = fmaxf(o0.x + bv0.x, 0.f); o0.y = fmaxf(o0.y + bv0.y, 0.f);
            o0.z = fmaxf(o0.z + bv0.z, 0.f); o0.w = fmaxf(o0.w + bv0.w, 0.f);
            o1.x = fmaxf(o1.x + bv1.x, 0.f); o1.y = fmaxf(o1.y + bv1.y, 0.f);
            o1.z = fmaxf(o1.z + bv1.z, 0.f); o1.w = fmaxf(o1.w + bv1.w, 0.f);
        }
        *(float4*)&C[(size_t)row * NCOL + colb]     = o0;
        *(float4*)&C[(size_t)row * NCOL + colb + 4] = o1;
    }
}

// ---------------- launch (kernel launches ONLY — graph-capture safe) ----------------
extern "C" void kernel_launch(void* const* d_in, const int* in_sizes, int n_in,
                              void* d_out, int out_size) {
    const float* x   = (const float*)d_in[0];
    const int*   ei  = (const int*)d_in[1];   // raw words; dtype detected on device
    const float* W1  = (const float*)d_in[2];
    const float* b1  = (const float*)d_in[3];
    const float* W2  = (const float*)d_in[4];
    const float* b2  = (const float*)d_in[5];
    float*       out = (float*)d_out;

    // edge_index normalization + graph preprocessing
    k_detect<<<1, 32>>>(ei);
    k_deg_init<<<(NN + 255) / 256, 256>>>();
    k_decode<<<(2 * EE + 255) / 256, 256>>>(ei);   // decode + fused degree count
    k_scan<<<1, 1024>>>();                         // rowptr + cursor + dis
    k_fill<<<(ETOT + 255) / 256, 256>>>();

    // layer 1: agg1 = A_hat * x ; h1 = relu(agg1 @ W1 + b1)
    k_spmm128<1><<<(NN * 32 + 255) / 256, 256>>>(x, nullptr, nullptr);
    dim3 g1(FHID / 128, (NN + 127) / 128);
    k_gemm2<1, FIN, FHID><<<g1, 256>>>(W1, b1);

    // layer 2: g2 = h1 @ W2 ; out = relu(A_hat * g2 + b2)
    dim3 g2d(FOUT / 128, (NN + 127) / 128);
    k_gemm2<2, FHID, FOUT><<<g2d, 256>>>(W2, nullptr);
    k_spmm128<2><<<(NN * 32 + 255) / 256, 256>>>(nullptr, out, b2);
}

// round 7
// speedup vs baseline: 1.3472x; 1.3472x over previous
#include <cuda_runtime.h>

#define NN   50000
#define EE   800000
#define FIN  128
#define FHID 256
#define FOUT 128
#define ETOT (EE + NN)
#define NBLK ((NN + 255) / 256)   // 196 scan blocks

// ---------------- device scratch (no allocations allowed) ----------------
__device__ int   g_is64;
__device__ int   g_ei[2 * EE];               // decoded edge_index (int32)
__device__ int   g_deg[NN];
__device__ int   g_bsum[NBLK];
__device__ int   g_boff[NBLK];
__device__ int   g_rowptr[NN + 1];
__device__ int   g_cursor[NN];
__device__ int   g_col[ETOT];
__device__ float g_w[ETOT];
__device__ float g_dis[NN];
__device__ float g_agg1[(size_t)NN * FIN];   // 25.6 MB
__device__ float g_h1[(size_t)NN * FHID];    // 51.2 MB
__device__ float g_g2[(size_t)NN * FOUT];    // 25.6 MB

// ---------------- edge_index dtype detection + decode ----------------
__global__ void k_detect(const int* __restrict__ ei_raw) {
    if (threadIdx.x == 0) {
        int is64 = 1;
        for (int i = 1; i < 64; i += 2)
            if (ei_raw[i] != 0) { is64 = 0; break; }
        g_is64 = is64;
    }
}

__global__ void k_decode(const int* __restrict__ ei_raw) {
    int e = blockIdx.x * blockDim.x + threadIdx.x;
    if (e >= 2 * EE) return;
    int v = g_is64 ? ei_raw[2 * e] : ei_raw[e];
    v = min(max(v, 0), NN - 1);   // defensive clamp
    g_ei[e] = v;
}

// ---------------- graph preprocessing ----------------
__global__ void k_deg_init() {
    int i = blockIdx.x * blockDim.x + threadIdx.x;
    if (i < NN) g_deg[i] = 1;  // self-loop
}

__global__ void k_deg_count() {
    int e = blockIdx.x * blockDim.x + threadIdx.x;
    if (e < EE) atomicAdd(&g_deg[g_ei[EE + e]], 1);
}

// ---- 3-phase parallel exclusive scan of g_deg (replaces 111us single-block scan) ----
__global__ void k_bsum() {
    __shared__ int sh[256];
    int t = threadIdx.x;
    int i = blockIdx.x * 256 + t;
    int d = (i < NN) ? g_deg[i] : 0;
    sh[t] = d;
    __syncthreads();
    for (int off = 128; off > 0; off >>= 1) {
        if (t < off) sh[t] += sh[t + off];
        __syncthreads();
    }
    if (t == 0) g_bsum[blockIdx.x] = sh[0];
}

__global__ void k_bscan() {   // 1 block, 256 threads, scans NBLK block sums
    __shared__ int sh[256];
    int t = threadIdx.x;
    int v = (t < NBLK) ? g_bsum[t] : 0;
    sh[t] = v;
    __syncthreads();
    for (int off = 1; off < 256; off <<= 1) {
        int u = (t >= off) ? sh[t - off] : 0;
        __syncthreads();
        sh[t] += u;
        __syncthreads();
    }
    if (t < NBLK) g_boff[t] = sh[t] - v;   // exclusive
}

__global__ void k_emit() {
    __shared__ int sh[256];
    int t = threadIdx.x;
    int i = blockIdx.x * 256 + t;
    int d = (i < NN) ? g_deg[i] : 0;
    sh[t] = d;
    __syncthreads();
    for (int off = 1; off < 256; off <<= 1) {
        int u = (t >= off) ? sh[t - off] : 0;
        __syncthreads();
        sh[t] += u;
        __syncthreads();
    }
    int pref = g_boff[blockIdx.x] + sh[t] - d;   // exclusive prefix
    if (i < NN) {
        g_rowptr[i] = pref;
        g_cursor[i] = pref;
        g_dis[i]    = rsqrtf((float)d);
        if (i == NN - 1) g_rowptr[NN] = pref + d;
    }
}

__global__ void k_fill() {
    int e = blockIdx.x * blockDim.x + threadIdx.x;
    if (e >= ETOT) return;
    int s, d;
    if (e < EE) { s = g_ei[e]; d = g_ei[EE + e]; }
    else        { s = d = e - EE; }            // self-loop edges
    int pos = atomicAdd(&g_cursor[d], 1);
    g_col[pos] = s;
    g_w[pos]   = g_dis[s] * g_dis[d];
}

// ---------------- SpMM: out[r,:] = sum_e w[e] * in[col[e],:]  (F = 128) -------------
template <int LAYER>
__global__ void k_spmm128(const float* __restrict__ xin, float* __restrict__ xout,
                          const float* __restrict__ bias) {
    const float* in  = (LAYER == 1) ? xin : (const float*)g_g2;
    float*       out = (LAYER == 1) ? (float*)g_agg1 : xout;

    int warp = (blockIdx.x * blockDim.x + threadIdx.x) >> 5;
    int lane = threadIdx.x & 31;
    if (warp >= NN) return;
    int start = g_rowptr[warp];
    int end   = g_rowptr[warp + 1];
    const float4* in4 = (const float4*)in;
    float4 acc = make_float4(0.f, 0.f, 0.f, 0.f);

    for (int e0 = start; e0 < end; e0 += 32) {
        int e = e0 + lane;
        int   c  = 0;
        float wv = 0.f;
        if (e < end) { c = g_col[e]; wv = g_w[e]; }
        int cnt = min(32, end - e0);
        for (int j = 0; j < cnt; j++) {
            int   cj = __shfl_sync(0xffffffffu, c,  j);
            float wj = __shfl_sync(0xffffffffu, wv, j);
            float4 v = __ldg(&in4[(size_t)cj * 32 + lane]);
            acc.x = fmaf(wj, v.x, acc.x);
            acc.y = fmaf(wj, v.y, acc.y);
            acc.z = fmaf(wj, v.z, acc.z);
            acc.w = fmaf(wj, v.w, acc.w);
        }
    }
    if (LAYER == 2) {  // fuse bias + relu
        float4 b = ((const float4*)bias)[lane];
        acc.x = fmaxf(acc.x + b.x, 0.f);
        acc.y = fmaxf(acc.y + b.y, 0.f);
        acc.z = fmaxf(acc.z + b.z, 0.f);
        acc.w = fmaxf(acc.w + b.w, 0.f);
    }
    ((float4*)out)[(size_t)warp * 32 + lane] = acc;
}

// ---------------- GEMM: C[M,NCOL] = A[M,K] @ B[K,NCOL]  (R5 known-good) -------------
// BM=128, BN=64, BK=8, 256 threads, 8x4 micro-tile.
template <int LAYER, int K, int NCOL>
__global__ __launch_bounds__(256) void k_gemm(
    const float* __restrict__ B, const float* __restrict__ bias) {
    const float* A = (LAYER == 1) ? (const float*)g_agg1 : (const float*)g_h1;
    float*       C = (LAYER == 1) ? (float*)g_h1 : (float*)g_g2;
    const int M = NN;

    __shared__ float As[8][128];
    __shared__ float Bs[8][64];
    int t  = threadIdx.x;
    int tx = t & 15;   // 16 -> 4 cols each
    int ty = t >> 4;   // 16 -> 8 rows each
    int m0 = blockIdx.y * 128;
    int n0 = blockIdx.x * 64;

    float acc[8][4];
#pragma unroll
    for (int i = 0; i < 8; i++)
#pragma unroll
        for (int j = 0; j < 4; j++) acc[i][j] = 0.f;

    int a_m  = t >> 1;         // 0..127
    int a_k4 = (t & 1) * 4;    // 0 or 4
    int arow = m0 + a_m;

    for (int kk = 0; kk < K; kk += 8) {
        float4 av = make_float4(0.f, 0.f, 0.f, 0.f);
        if (arow < M)
            av = *(const float4*)&A[(size_t)arow * K + kk + a_k4];
        As[a_k4 + 0][a_m] = av.x;
        As[a_k4 + 1][a_m] = av.y;
        As[a_k4 + 2][a_m] = av.z;
        As[a_k4 + 3][a_m] = av.w;
        if (t < 128) {
            int bk = t >> 4;
            int bc = (t & 15) * 4;
            *(float4*)&Bs[bk][bc] =
                *(const float4*)&B[(size_t)(kk + bk) * NCOL + n0 + bc];
        }
        __syncthreads();
#pragma unroll
        for (int k = 0; k < 8; k++) {
            float a[8], b[4];
#pragma unroll
            for (int i = 0; i < 8; i++) a[i] = As[k][ty * 8 + i];
#pragma unroll
            for (int j = 0; j < 4; j++) b[j] = Bs[k][tx * 4 + j];
#pragma unroll
            for (int i = 0; i < 8; i++)
#pragma unroll
                for (int j = 0; j < 4; j++)
                    acc[i][j] = fmaf(a[i], b[j], acc[i][j]);
        }
        __syncthreads();
    }

    int colb = n0 + tx * 4;
    float4 bv = make_float4(0.f, 0.f, 0.f, 0.f);
    if (LAYER == 1) bv = *(const float4*)&bias[colb];
#pragma unroll
    for (int i = 0; i < 8; i++) {
        int row = m0 + ty * 8 + i;
        if (row >= M) continue;
        float4 o = make_float4(acc[i][0], acc[i][1], acc[i][2], acc[i][3]);
        if (LAYER == 1) {  // fuse bias + relu
            o.x = fmaxf(o.x + bv.x, 0.f);
            o.y = fmaxf(o.y + bv.y, 0.f);
            o.z = fmaxf(o.z + bv.z, 0.f);
            o.w = fmaxf(o.w + bv.w, 0.f);
        }
        *(float4*)&C[(size_t)row * NCOL + colb] = o;
    }
}

// ---------------- launch (kernel launches ONLY — graph-capture safe) ----------------
extern "C" void kernel_launch(void* const* d_in, const int* in_sizes, int n_in,
                              void* d_out, int out_size) {
    const float* x   = (const float*)d_in[0];
    const int*   ei  = (const int*)d_in[1];   // raw words; dtype detected on device
    const float* W1  = (const float*)d_in[2];
    const float* b1  = (const float*)d_in[3];
    const float* W2  = (const float*)d_in[4];
    const float* b2  = (const float*)d_in[5];
    float*       out = (float*)d_out;

    // edge_index normalization + graph preprocessing
    k_detect<<<1, 32>>>(ei);
    k_decode<<<(2 * EE + 255) / 256, 256>>>(ei);
    k_deg_init<<<(NN + 255) / 256, 256>>>();
    k_deg_count<<<(EE + 255) / 256, 256>>>();
    k_bsum<<<NBLK, 256>>>();
    k_bscan<<<1, 256>>>();
    k_emit<<<NBLK, 256>>>();
    k_fill<<<(ETOT + 255) / 256, 256>>>();

    // layer 1: agg1 = A_hat * x ; h1 = relu(agg1 @ W1 + b1)
    k_spmm128<1><<<(NN * 32 + 255) / 256, 256>>>(x, nullptr, nullptr);
    dim3 g1(FHID / 64, (NN + 127) / 128);
    k_gemm<1, FIN, FHID><<<g1, 256>>>(W1, b1);

    // layer 2: g2 = h1 @ W2 ; out = relu(A_hat * g2 + b2)
    dim3 g2d(FOUT / 64, (NN + 127) / 128);
    k_gemm<2, FHID, FOUT><<<g2d, 256>>>(W2, nullptr);
    k_spmm128<2><<<(NN * 32 + 255) / 256, 256>>>(nullptr, out, b2);
}